// round 2
// baseline (speedup 1.0000x reference)
#include <cuda_runtime.h>
#include <cuda.h>
#include <cstdint>

// ============================================================================
// GraphConvolution: out = adj[16384,16384] @ (x[16384,64] @ W[64,64]) + bias
//
// Toolchain compiles device PTX for target sm_103 (no 'a'): tcgen05/TMEM are
// unavailable, but TMA (cp.async.bulk.tensor) + mbarrier ARE available
// (verified: round-1 ptxas rejected only tcgen05 lines).
//
// Kernel 1: supT[n][k] = tf32(sum_i x[k][i]*W[i][n])  (K-major B operand)
// Kernel 2: out = adj @ support via mma.sync tf32 m16n8k8, TMA-fed
//           8-stage producer/consumer pipeline, SW128 swizzled smem.
// ============================================================================

#define N_ROWS 16384
#define K_DIM  16384
#define IN_F   64
#define OUT_F  64

#define TILE_M 128
#define TILE_K 32                       // 32 fp32 = 128 B = SW128 atom row
#define STAGES 8
#define N_ITERS (K_DIM / TILE_K)        // 512

#define ADJ_TILE_BYTES (TILE_M * 128)   // 16384
#define B_TILE_BYTES   (OUT_F * 128)    // 8192
#define STAGE_BYTES    (ADJ_TILE_BYTES + B_TILE_BYTES)  // 24576

#define OFF_BARS  0                     // per stage: full @ 16*s, empty @ 16*s+8
#define OFF_TILES 1024
#define SMEM_BYTES (OFF_TILES + STAGES * STAGE_BYTES)   // 197632

#define N_CWARPS 4                      // compute warps; each owns 32x64 slice

// ---------------------------------------------------------------- PTX helpers
__device__ __forceinline__ uint32_t smem_to_u32(const void* p) {
    uint32_t a;
    asm("{ .reg .u64 t; cvta.to.shared.u64 t, %1; cvt.u32.u64 %0, t; }" : "=r"(a) : "l"(p));
    return a;
}

#define MBARRIER_INIT(addr, count) \
    asm volatile("mbarrier.init.shared.b64 [%0], %1;" :: "r"((uint32_t)(addr)), "r"((uint32_t)(count)) : "memory")

#define MBARRIER_ARRIVE(addr) \
    asm volatile("mbarrier.arrive.shared.b64 _, [%0];" :: "r"((uint32_t)(addr)) : "memory")

#define MBARRIER_EXPECT_TX(addr, bytes) \
    asm volatile("mbarrier.arrive.expect_tx.shared.b64 _, [%0], %1;" :: "r"((uint32_t)(addr)), "r"((uint32_t)(bytes)) : "memory")

#define MBARRIER_WAIT_PARITY(addr, parity) do {                                      \
    uint32_t _mbar = (uint32_t)(addr);                                               \
    uint32_t _par  = (uint32_t)(parity);                                             \
    uint32_t _done;                                                                  \
    asm volatile(                                                                    \
        "{\n\t.reg .pred p;\n\t"                                                     \
        "mbarrier.try_wait.parity.acquire.cta.shared::cta.b64 p, [%1], %2;\n\t"      \
        "selp.b32 %0, 1, 0, p;\n\t}"                                                 \
        : "=r"(_done) : "r"(_mbar), "r"(_par) : "memory");                           \
    if (!_done) {                                                                    \
        asm volatile(                                                                \
            "{\n\t.reg .pred P1;\n\t"                                                \
            "WAIT_LOOP_%=:\n\t"                                                      \
            "mbarrier.try_wait.parity.acquire.cta.shared::cta.b64 P1, [%0], %1, 0x989680;\n\t" \
            "@P1 bra.uni WAIT_DONE_%=;\n\t"                                          \
            "bra.uni WAIT_LOOP_%=;\n\t"                                              \
            "WAIT_DONE_%=:\n\t}"                                                     \
            :: "r"(_mbar), "r"(_par) : "memory");                                    \
    }                                                                                \
} while (0)

__device__ __forceinline__ void tma_load_2d_g(uint32_t smem_addr, const CUtensorMap* map,
                                              int cx, int cy, uint32_t mbar) {
    asm volatile(
        "cp.async.bulk.tensor.2d.shared::cta.global.tile.mbarrier::complete_tx::bytes "
        "[%0], [%1, {%2, %3}], [%4];"
        :: "r"(smem_addr), "l"(map), "r"(cx), "r"(cy), "r"(mbar) : "memory");
}

__device__ __forceinline__ uint32_t lds32(uint32_t a) {
    uint32_t v;
    asm volatile("ld.shared.b32 %0, [%1];" : "=r"(v) : "r"(a));
    return v;
}

__device__ __forceinline__ uint32_t f2tf32(uint32_t bits) {
    uint32_t o;
    asm("cvt.rna.tf32.f32 %0, %1;" : "=r"(o) : "f"(__uint_as_float(bits)));
    return o;
}

__device__ __forceinline__ void mma_tf32(float* c,
                                         uint32_t a0, uint32_t a1, uint32_t a2, uint32_t a3,
                                         uint32_t b0, uint32_t b1) {
    asm volatile(
        "mma.sync.aligned.m16n8k8.row.col.f32.tf32.tf32.f32 "
        "{%0,%1,%2,%3}, {%4,%5,%6,%7}, {%8,%9}, {%0,%1,%2,%3};"
        : "+f"(c[0]), "+f"(c[1]), "+f"(c[2]), "+f"(c[3])
        : "r"(a0), "r"(a1), "r"(a2), "r"(a3), "r"(b0), "r"(b1));
}

// ---------------------------------------------------------------- scratch
__device__ __align__(1024) float g_supT[(size_t)OUT_F * K_DIM];  // 4 MiB

// ---------------------------------------------------------------- kernel 1
__global__ void __launch_bounds__(128) gcn_support_kernel(const float* __restrict__ x,
                                                          const float* __restrict__ w,
                                                          float* __restrict__ supT) {
    __shared__ float ws[IN_F * OUT_F];
    int tid = threadIdx.x;
    for (int i = tid; i < IN_F * OUT_F; i += 128) ws[i] = w[i];
    __syncthreads();

    int k = blockIdx.x * 128 + tid;
    float xr[IN_F];
    const float4* xv = reinterpret_cast<const float4*>(x + (size_t)k * IN_F);
#pragma unroll
    for (int i = 0; i < IN_F / 4; i++) {
        float4 v = xv[i];
        xr[4 * i] = v.x; xr[4 * i + 1] = v.y; xr[4 * i + 2] = v.z; xr[4 * i + 3] = v.w;
    }
    for (int n = 0; n < OUT_F; n++) {
        float acc = 0.f;
#pragma unroll
        for (int i = 0; i < IN_F; i++) acc = fmaf(xr[i], ws[i * OUT_F + n], acc);
        uint32_t t;
        asm("cvt.rna.tf32.f32 %0, %1;" : "=r"(t) : "f"(acc));  // pre-round to tf32
        supT[(size_t)n * K_DIM + k] = __uint_as_float(t);
    }
}

// ---------------------------------------------------------------- kernel 2
// 5 warps: wid 0..3 compute (each a 32x64 output slice), wid 4 = TMA producer.
__global__ void __launch_bounds__(160, 1) gcn_gemm_kernel(
    const __grid_constant__ CUtensorMap madj,
    const __grid_constant__ CUtensorMap msup,
    float* __restrict__ out,
    const float* __restrict__ bias)
{
    extern __shared__ char smem[];
    uint32_t sb = smem_to_u32(smem);
    int tid = threadIdx.x;
    int wid = tid >> 5;
    int lid = tid & 31;
    int m0 = blockIdx.x * TILE_M;

    if (tid == 0) {
        for (int s = 0; s < STAGES; s++) {
            MBARRIER_INIT(sb + OFF_BARS + s * 16, 1);            // full: 1 expect_tx
            MBARRIER_INIT(sb + OFF_BARS + s * 16 + 8, N_CWARPS); // empty: 4 warp arrives
        }
    }
    __syncthreads();

    if (wid == 4) {
        if (lid == 0) {
            // -------- producer: TMA loads, backpressured by empty barriers
            int s = 0; uint32_t ph = 1;  // flipped phase: first STAGES waits pass
            for (int it = 0; it < N_ITERS; it++) {
                uint32_t fb = sb + OFF_BARS + s * 16;
                MBARRIER_WAIT_PARITY(fb + 8, ph);
                MBARRIER_EXPECT_TX(fb, STAGE_BYTES);
                uint32_t a_sm = sb + OFF_TILES + s * STAGE_BYTES;
                tma_load_2d_g(a_sm,                  &madj, it * TILE_K, m0, fb);
                tma_load_2d_g(a_sm + ADJ_TILE_BYTES, &msup, it * TILE_K, 0,  fb);
                if (++s == STAGES) { s = 0; ph ^= 1; }
            }
        }
        return;
    }

    // -------- compute warps: mma.sync tf32 m16n8k8, register accumulators
    int g = lid >> 2;          // 0..7
    int t = lid & 3;           // 0..3
    uint32_t xorv = (uint32_t)g << 4;   // SW128 swizzle term (row&7 == g here)

    // Row byte offsets within the A tile: warp w rows [32w, 32w+32)
    uint32_t rA0 = (uint32_t)(wid * 32 + g) * 128;   // mt0, upper 8
    // mt0 lower = rA0+1024 ; mt1 = rA0+2048 / +3072
    uint32_t rB[8];
#pragma unroll
    for (int nt = 0; nt < 8; nt++) rB[nt] = (uint32_t)(nt * 8 + g) * 128;

    float acc[2][8][4];
#pragma unroll
    for (int mt = 0; mt < 2; mt++)
#pragma unroll
        for (int nt = 0; nt < 8; nt++)
#pragma unroll
            for (int c = 0; c < 4; c++) acc[mt][nt][c] = 0.f;

    int s = 0; uint32_t ph = 0;
    for (int it = 0; it < N_ITERS; it++) {
        uint32_t fb = sb + OFF_BARS + s * 16;
        MBARRIER_WAIT_PARITY(fb, ph);
        uint32_t sA = sb + OFF_TILES + s * STAGE_BYTES;
        uint32_t sB = sA + ADJ_TILE_BYTES;

#pragma unroll
        for (int ks = 0; ks < 4; ks++) {
            uint32_t cb0 = (uint32_t)(ks * 32 + t * 4) ^ xorv;        // col t
            uint32_t cb1 = (uint32_t)(ks * 32 + t * 4 + 16) ^ xorv;   // col t+4

            // A fragments for mt0, mt1 (rna-rounded to tf32)
            uint32_t a00 = f2tf32(lds32(sA + rA0 + cb0));
            uint32_t a01 = f2tf32(lds32(sA + rA0 + 1024 + cb0));
            uint32_t a02 = f2tf32(lds32(sA + rA0 + cb1));
            uint32_t a03 = f2tf32(lds32(sA + rA0 + 1024 + cb1));
            uint32_t a10 = f2tf32(lds32(sA + rA0 + 2048 + cb0));
            uint32_t a11 = f2tf32(lds32(sA + rA0 + 3072 + cb0));
            uint32_t a12 = f2tf32(lds32(sA + rA0 + 2048 + cb1));
            uint32_t a13 = f2tf32(lds32(sA + rA0 + 3072 + cb1));

#pragma unroll
            for (int nt = 0; nt < 8; nt++) {
                uint32_t b0 = lds32(sB + rB[nt] + cb0);   // supT pre-rounded
                uint32_t b1 = lds32(sB + rB[nt] + cb1);
                mma_tf32(acc[0][nt], a00, a01, a02, a03, b0, b1);
                mma_tf32(acc[1][nt], a10, a11, a12, a13, b0, b1);
            }
        }
        if (lid == 0) MBARRIER_ARRIVE(fb + 8);
        if (++s == STAGES) { s = 0; ph ^= 1; }
    }

    // -------- epilogue: bias + store (c0,c1)->(row,col), (c2,c3)->(row+8,col)
    const float2* b2 = reinterpret_cast<const float2*>(bias);
    int row0 = m0 + wid * 32 + g;            // mt0 upper
#pragma unroll
    for (int mt = 0; mt < 2; mt++) {
        int r = row0 + mt * 16;
#pragma unroll
        for (int nt = 0; nt < 8; nt++) {
            int col = nt * 8 + 2 * t;
            float2 bv = b2[col >> 1];
            float2 v0, v1;
            v0.x = acc[mt][nt][0] + bv.x;  v0.y = acc[mt][nt][1] + bv.y;
            v1.x = acc[mt][nt][2] + bv.x;  v1.y = acc[mt][nt][3] + bv.y;
            *reinterpret_cast<float2*>(out + (size_t)r * OUT_F + col) = v0;
            *reinterpret_cast<float2*>(out + (size_t)(r + 8) * OUT_F + col) = v1;
        }
    }
}

// ---------------------------------------------------------------- host
typedef CUresult (*tmap_encode_fn)(
    CUtensorMap*, CUtensorMapDataType, cuuint32_t, void*,
    const cuuint64_t*, const cuuint64_t*, const cuuint32_t*, const cuuint32_t*,
    CUtensorMapInterleave, CUtensorMapSwizzle, CUtensorMapL2promotion,
    CUtensorMapFloatOOBfill);

extern "C" void kernel_launch(void* const* d_in, const int* in_sizes, int n_in,
                              void* d_out, int out_size) {
    const float* x    = (const float*)d_in[0];
    const float* adj  = (const float*)d_in[1];
    const float* w    = (const float*)d_in[2];
    const float* bias = (const float*)d_in[3];
    float* out = (float*)d_out;

    void* supT_ptr = nullptr;
    cudaGetSymbolAddress(&supT_ptr, g_supT);
    float* supT = (float*)supT_ptr;

    gcn_support_kernel<<<K_DIM / 128, 128>>>(x, w, supT);

    // Driver entry point via cudart (no -lcuda link dependency)
    tmap_encode_fn enc = nullptr;
    cudaDriverEntryPointQueryResult qr;
    cudaGetDriverEntryPointByVersion("cuTensorMapEncodeTiled", (void**)&enc, 12000,
                                     cudaEnableDefault, &qr);

    CUtensorMap madj{}, msup{};
    {
        cuuint64_t dims[2]    = {(cuuint64_t)K_DIM, (cuuint64_t)N_ROWS};
        cuuint64_t strides[1] = {(cuuint64_t)K_DIM * sizeof(float)};
        cuuint32_t box[2]     = {TILE_K, TILE_M};   // 128B x 128 rows, SW128
        cuuint32_t es[2]      = {1, 1};
        enc(&madj, CU_TENSOR_MAP_DATA_TYPE_FLOAT32, 2, (void*)adj,
            dims, strides, box, es,
            CU_TENSOR_MAP_INTERLEAVE_NONE, CU_TENSOR_MAP_SWIZZLE_128B,
            CU_TENSOR_MAP_L2_PROMOTION_L2_128B, CU_TENSOR_MAP_FLOAT_OOB_FILL_NONE);
    }
    {
        cuuint64_t dims[2]    = {(cuuint64_t)K_DIM, (cuuint64_t)OUT_F};
        cuuint64_t strides[1] = {(cuuint64_t)K_DIM * sizeof(float)};
        cuuint32_t box[2]     = {TILE_K, OUT_F};    // 128B x 64 rows, SW128
        cuuint32_t es[2]      = {1, 1};
        enc(&msup, CU_TENSOR_MAP_DATA_TYPE_FLOAT32, 2, (void*)supT,
            dims, strides, box, es,
            CU_TENSOR_MAP_INTERLEAVE_NONE, CU_TENSOR_MAP_SWIZZLE_128B,
            CU_TENSOR_MAP_L2_PROMOTION_L2_128B, CU_TENSOR_MAP_FLOAT_OOB_FILL_NONE);
    }

    cudaFuncSetAttribute(gcn_gemm_kernel, cudaFuncAttributeMaxDynamicSharedMemorySize,
                         SMEM_BYTES);
    gcn_gemm_kernel<<<N_ROWS / TILE_M, 160, SMEM_BYTES>>>(madj, msup, out, bias);
}

// round 3
// speedup vs baseline: 1.1512x; 1.1512x over previous
#include <cuda_runtime.h>
#include <cuda.h>
#include <cstdint>

// ============================================================================
// GraphConvolution: out = adj[16384,16384] @ (x[16384,64] @ W[64,64]) + bias
//
// Round 3: K-split warp specialization. 8 compute warps (2 per SMSP):
//   group 0 (wid 0-3): ks 0,1 of each 32-wide k-tile
//   group 1 (wid 4-7): ks 2,3
// Each group holds full 128x64 accumulators; one smem reduction at the end.
// TMA-fed 8-stage pipeline unchanged (producer = warp 8).
// ============================================================================

#define N_ROWS 16384
#define K_DIM  16384
#define IN_F   64
#define OUT_F  64

#define TILE_M 128
#define TILE_K 32                       // 32 fp32 = 128 B = SW128 atom row
#define STAGES 8
#define N_ITERS (K_DIM / TILE_K)        // 512

#define ADJ_TILE_BYTES (TILE_M * 128)   // 16384
#define B_TILE_BYTES   (OUT_F * 128)    // 8192
#define STAGE_BYTES    (ADJ_TILE_BYTES + B_TILE_BYTES)  // 24576

#define OFF_BARS  0                     // per stage: full @ 16*s, empty @ 16*s+8
#define OFF_TILES 1024
#define SMEM_BYTES (OFF_TILES + STAGES * STAGE_BYTES)   // 197632

#define N_CWARPS 8
#define PART_STRIDE 66                  // padded row stride (floats) for reduction

// ---------------------------------------------------------------- PTX helpers
__device__ __forceinline__ uint32_t smem_to_u32(const void* p) {
    uint32_t a;
    asm("{ .reg .u64 t; cvta.to.shared.u64 t, %1; cvt.u32.u64 %0, t; }" : "=r"(a) : "l"(p));
    return a;
}

#define MBARRIER_INIT(addr, count) \
    asm volatile("mbarrier.init.shared.b64 [%0], %1;" :: "r"((uint32_t)(addr)), "r"((uint32_t)(count)) : "memory")

#define MBARRIER_ARRIVE(addr) \
    asm volatile("mbarrier.arrive.shared.b64 _, [%0];" :: "r"((uint32_t)(addr)) : "memory")

#define MBARRIER_EXPECT_TX(addr, bytes) \
    asm volatile("mbarrier.arrive.expect_tx.shared.b64 _, [%0], %1;" :: "r"((uint32_t)(addr)), "r"((uint32_t)(bytes)) : "memory")

#define MBARRIER_WAIT_PARITY(addr, parity) do {                                      \
    uint32_t _mbar = (uint32_t)(addr);                                               \
    uint32_t _par  = (uint32_t)(parity);                                             \
    uint32_t _done;                                                                  \
    asm volatile(                                                                    \
        "{\n\t.reg .pred p;\n\t"                                                     \
        "mbarrier.try_wait.parity.acquire.cta.shared::cta.b64 p, [%1], %2;\n\t"      \
        "selp.b32 %0, 1, 0, p;\n\t}"                                                 \
        : "=r"(_done) : "r"(_mbar), "r"(_par) : "memory");                           \
    if (!_done) {                                                                    \
        asm volatile(                                                                \
            "{\n\t.reg .pred P1;\n\t"                                                \
            "WAIT_LOOP_%=:\n\t"                                                      \
            "mbarrier.try_wait.parity.acquire.cta.shared::cta.b64 P1, [%0], %1, 0x989680;\n\t" \
            "@P1 bra.uni WAIT_DONE_%=;\n\t"                                          \
            "bra.uni WAIT_LOOP_%=;\n\t"                                              \
            "WAIT_DONE_%=:\n\t}"                                                     \
            :: "r"(_mbar), "r"(_par) : "memory");                                    \
    }                                                                                \
} while (0)

__device__ __forceinline__ void tma_load_2d_g(uint32_t smem_addr, const CUtensorMap* map,
                                              int cx, int cy, uint32_t mbar) {
    asm volatile(
        "cp.async.bulk.tensor.2d.shared::cta.global.tile.mbarrier::complete_tx::bytes "
        "[%0], [%1, {%2, %3}], [%4];"
        :: "r"(smem_addr), "l"(map), "r"(cx), "r"(cy), "r"(mbar) : "memory");
}

__device__ __forceinline__ uint32_t lds32(uint32_t a) {
    uint32_t v;
    asm volatile("ld.shared.b32 %0, [%1];" : "=r"(v) : "r"(a));
    return v;
}

__device__ __forceinline__ uint32_t f2tf32(uint32_t bits) {
    uint32_t o;
    asm("cvt.rna.tf32.f32 %0, %1;" : "=r"(o) : "f"(__uint_as_float(bits)));
    return o;
}

__device__ __forceinline__ void mma_tf32(float* c,
                                         uint32_t a0, uint32_t a1, uint32_t a2, uint32_t a3,
                                         uint32_t b0, uint32_t b1) {
    asm volatile(
        "mma.sync.aligned.m16n8k8.row.col.f32.tf32.tf32.f32 "
        "{%0,%1,%2,%3}, {%4,%5,%6,%7}, {%8,%9}, {%0,%1,%2,%3};"
        : "+f"(c[0]), "+f"(c[1]), "+f"(c[2]), "+f"(c[3])
        : "r"(a0), "r"(a1), "r"(a2), "r"(a3), "r"(b0), "r"(b1));
}

// ---------------------------------------------------------------- scratch
__device__ __align__(1024) float g_supT[(size_t)OUT_F * K_DIM];  // 4 MiB

// ---------------------------------------------------------------- kernel 1
// 256 threads: tid&127 -> k-row within block slab, tid>>7 -> half of n range.
__global__ void __launch_bounds__(256) gcn_support_kernel(const float* __restrict__ x,
                                                          const float* __restrict__ w,
                                                          float* __restrict__ supT) {
    __shared__ float ws[IN_F * OUT_F];
    int tid = threadIdx.x;
    for (int i = tid; i < IN_F * OUT_F; i += 256) ws[i] = w[i];
    __syncthreads();

    int k  = blockIdx.x * 128 + (tid & 127);
    int n0 = (tid >> 7) * (OUT_F / 2);

    float xr[IN_F];
    const float4* xv = reinterpret_cast<const float4*>(x + (size_t)k * IN_F);
#pragma unroll
    for (int i = 0; i < IN_F / 4; i++) {
        float4 v = xv[i];
        xr[4 * i] = v.x; xr[4 * i + 1] = v.y; xr[4 * i + 2] = v.z; xr[4 * i + 3] = v.w;
    }
#pragma unroll 4
    for (int nn = 0; nn < OUT_F / 2; nn++) {
        int n = n0 + nn;
        float acc = 0.f;
#pragma unroll
        for (int i = 0; i < IN_F; i++) acc = fmaf(xr[i], ws[i * OUT_F + n], acc);
        uint32_t t;
        asm("cvt.rna.tf32.f32 %0, %1;" : "=r"(t) : "f"(acc));  // pre-round to tf32
        supT[(size_t)n * K_DIM + k] = __uint_as_float(t);
    }
}

// ---------------------------------------------------------------- kernel 2
// 9 warps: wid 0..7 compute (K-split groups), wid 8 = TMA producer.
__global__ void __launch_bounds__(288, 1) gcn_gemm_kernel(
    const __grid_constant__ CUtensorMap madj,
    const __grid_constant__ CUtensorMap msup,
    float* __restrict__ out,
    const float* __restrict__ bias)
{
    extern __shared__ char smem[];
    uint32_t sb = smem_to_u32(smem);
    int tid = threadIdx.x;
    int wid = tid >> 5;
    int lid = tid & 31;
    int m0 = blockIdx.x * TILE_M;

    if (tid == 0) {
        for (int s = 0; s < STAGES; s++) {
            MBARRIER_INIT(sb + OFF_BARS + s * 16, 1);            // full: 1 expect_tx
            MBARRIER_INIT(sb + OFF_BARS + s * 16 + 8, N_CWARPS); // empty: 8 warp arrives
        }
    }
    __syncthreads();

    if (wid == 8) {
        if (lid == 0) {
            // -------- producer: TMA loads, backpressured by empty barriers
            int s = 0; uint32_t ph = 1;  // flipped phase: first STAGES waits pass
            for (int it = 0; it < N_ITERS; it++) {
                uint32_t fb = sb + OFF_BARS + s * 16;
                MBARRIER_WAIT_PARITY(fb + 8, ph);
                MBARRIER_EXPECT_TX(fb, STAGE_BYTES);
                uint32_t a_sm = sb + OFF_TILES + s * STAGE_BYTES;
                tma_load_2d_g(a_sm,                  &madj, it * TILE_K, m0, fb);
                tma_load_2d_g(a_sm + ADJ_TILE_BYTES, &msup, it * TILE_K, 0,  fb);
                if (++s == STAGES) { s = 0; ph ^= 1; }
            }
        }
        return;
    }

    // -------- compute warps
    int cwid   = wid & 3;      // row group: rows [32*cwid, 32*cwid+32)
    int kgroup = wid >> 2;     // 0 -> ks {0,1}, 1 -> ks {2,3}
    int g = lid >> 2;          // 0..7
    int t = lid & 3;           // 0..3
    uint32_t xorv = (uint32_t)g << 4;   // SW128 swizzle term (rows used are == g mod 8)

    uint32_t rA0 = (uint32_t)(cwid * 32 + g) * 128;   // mt0 upper 8 rows
    uint32_t rB[8];
#pragma unroll
    for (int nt = 0; nt < 8; nt++) rB[nt] = (uint32_t)(nt * 8 + g) * 128;

    float acc[2][8][4];
#pragma unroll
    for (int mt = 0; mt < 2; mt++)
#pragma unroll
        for (int nt = 0; nt < 8; nt++)
#pragma unroll
            for (int c = 0; c < 4; c++) acc[mt][nt][c] = 0.f;

    uint32_t ksbase = (uint32_t)(kgroup * 64);   // byte offset of this group's K half

    int s = 0; uint32_t ph = 0;
    for (int it = 0; it < N_ITERS; it++) {
        uint32_t fb = sb + OFF_BARS + s * 16;
        MBARRIER_WAIT_PARITY(fb, ph);
        uint32_t sA = sb + OFF_TILES + s * STAGE_BYTES;
        uint32_t sB = sA + ADJ_TILE_BYTES;

#pragma unroll
        for (int ks = 0; ks < 2; ks++) {
            uint32_t cb0 = (ksbase + (uint32_t)(ks * 32 + t * 4)) ^ xorv;        // col t
            uint32_t cb1 = (ksbase + (uint32_t)(ks * 32 + t * 4 + 16)) ^ xorv;   // col t+4

            uint32_t a00 = f2tf32(lds32(sA + rA0 + cb0));
            uint32_t a01 = f2tf32(lds32(sA + rA0 + 1024 + cb0));
            uint32_t a02 = f2tf32(lds32(sA + rA0 + cb1));
            uint32_t a03 = f2tf32(lds32(sA + rA0 + 1024 + cb1));
            uint32_t a10 = f2tf32(lds32(sA + rA0 + 2048 + cb0));
            uint32_t a11 = f2tf32(lds32(sA + rA0 + 3072 + cb0));
            uint32_t a12 = f2tf32(lds32(sA + rA0 + 2048 + cb1));
            uint32_t a13 = f2tf32(lds32(sA + rA0 + 3072 + cb1));

#pragma unroll
            for (int nt = 0; nt < 8; nt++) {
                uint32_t b0 = lds32(sB + rB[nt] + cb0);
                uint32_t b1 = lds32(sB + rB[nt] + cb1);
                mma_tf32(acc[0][nt], a00, a01, a02, a03, b0, b1);
                mma_tf32(acc[1][nt], a10, a11, a12, a13, b0, b1);
            }
        }
        if (lid == 0) MBARRIER_ARRIVE(fb + 8);
        if (++s == STAGES) { s = 0; ph ^= 1; }
    }

    // -------- reduction: group 1 writes partials to smem, group 0 adds
    float* part = reinterpret_cast<float*>(smem + OFF_TILES);
    if (kgroup == 1) {
#pragma unroll
        for (int mt = 0; mt < 2; mt++) {
            int r0 = cwid * 32 + mt * 16 + g;
#pragma unroll
            for (int nt = 0; nt < 8; nt++) {
                int col = nt * 8 + 2 * t;
                *reinterpret_cast<float2*>(part + (size_t)r0 * PART_STRIDE + col) =
                    make_float2(acc[mt][nt][0], acc[mt][nt][1]);
                *reinterpret_cast<float2*>(part + (size_t)(r0 + 8) * PART_STRIDE + col) =
                    make_float2(acc[mt][nt][2], acc[mt][nt][3]);
            }
        }
    }
    asm volatile("bar.sync 1, 256;" ::: "memory");

    if (kgroup == 0) {
        const float2* b2 = reinterpret_cast<const float2*>(bias);
        int row0 = m0 + cwid * 32 + g;
#pragma unroll
        for (int mt = 0; mt < 2; mt++) {
            int rloc = cwid * 32 + mt * 16 + g;
            int r = row0 + mt * 16;
#pragma unroll
            for (int nt = 0; nt < 8; nt++) {
                int col = nt * 8 + 2 * t;
                float2 bv = b2[col >> 1];
                float2 p0 = *reinterpret_cast<const float2*>(part + (size_t)rloc * PART_STRIDE + col);
                float2 p1 = *reinterpret_cast<const float2*>(part + (size_t)(rloc + 8) * PART_STRIDE + col);
                float2 v0, v1;
                v0.x = acc[mt][nt][0] + p0.x + bv.x;  v0.y = acc[mt][nt][1] + p0.y + bv.y;
                v1.x = acc[mt][nt][2] + p1.x + bv.x;  v1.y = acc[mt][nt][3] + p1.y + bv.y;
                *reinterpret_cast<float2*>(out + (size_t)r * OUT_F + col) = v0;
                *reinterpret_cast<float2*>(out + (size_t)(r + 8) * OUT_F + col) = v1;
            }
        }
    }
}

// ---------------------------------------------------------------- host
typedef CUresult (*tmap_encode_fn)(
    CUtensorMap*, CUtensorMapDataType, cuuint32_t, void*,
    const cuuint64_t*, const cuuint64_t*, const cuuint32_t*, const cuuint32_t*,
    CUtensorMapInterleave, CUtensorMapSwizzle, CUtensorMapL2promotion,
    CUtensorMapFloatOOBfill);

extern "C" void kernel_launch(void* const* d_in, const int* in_sizes, int n_in,
                              void* d_out, int out_size) {
    const float* x    = (const float*)d_in[0];
    const float* adj  = (const float*)d_in[1];
    const float* w    = (const float*)d_in[2];
    const float* bias = (const float*)d_in[3];
    float* out = (float*)d_out;

    void* supT_ptr = nullptr;
    cudaGetSymbolAddress(&supT_ptr, g_supT);
    float* supT = (float*)supT_ptr;

    gcn_support_kernel<<<K_DIM / 128, 256>>>(x, w, supT);

    // Driver entry point via cudart (no -lcuda link dependency)
    tmap_encode_fn enc = nullptr;
    cudaDriverEntryPointQueryResult qr;
    cudaGetDriverEntryPointByVersion("cuTensorMapEncodeTiled", (void**)&enc, 12000,
                                     cudaEnableDefault, &qr);

    CUtensorMap madj{}, msup{};
    {
        cuuint64_t dims[2]    = {(cuuint64_t)K_DIM, (cuuint64_t)N_ROWS};
        cuuint64_t strides[1] = {(cuuint64_t)K_DIM * sizeof(float)};
        cuuint32_t box[2]     = {TILE_K, TILE_M};   // 128B x 128 rows, SW128
        cuuint32_t es[2]      = {1, 1};
        enc(&madj, CU_TENSOR_MAP_DATA_TYPE_FLOAT32, 2, (void*)adj,
            dims, strides, box, es,
            CU_TENSOR_MAP_INTERLEAVE_NONE, CU_TENSOR_MAP_SWIZZLE_128B,
            CU_TENSOR_MAP_L2_PROMOTION_L2_128B, CU_TENSOR_MAP_FLOAT_OOB_FILL_NONE);
    }
    {
        cuuint64_t dims[2]    = {(cuuint64_t)K_DIM, (cuuint64_t)OUT_F};
        cuuint64_t strides[1] = {(cuuint64_t)K_DIM * sizeof(float)};
        cuuint32_t box[2]     = {TILE_K, OUT_F};    // 128B x 64 rows, SW128
        cuuint32_t es[2]      = {1, 1};
        enc(&msup, CU_TENSOR_MAP_DATA_TYPE_FLOAT32, 2, (void*)supT,
            dims, strides, box, es,
            CU_TENSOR_MAP_INTERLEAVE_NONE, CU_TENSOR_MAP_SWIZZLE_128B,
            CU_TENSOR_MAP_L2_PROMOTION_L2_128B, CU_TENSOR_MAP_FLOAT_OOB_FILL_NONE);
    }

    cudaFuncSetAttribute(gcn_gemm_kernel, cudaFuncAttributeMaxDynamicSharedMemorySize,
                         SMEM_BYTES);
    gcn_gemm_kernel<<<N_ROWS / TILE_M, 288, SMEM_BYTES>>>(madj, msup, out, bias);
}